// round 7
// baseline (speedup 1.0000x reference)
#include <cuda_runtime.h>
#include <cstdint>

// N=100000, E=1600000, D=8, K=1, C=32 (dims from in_sizes at runtime).
#define MAXN 100352
#define MAXE 1638400
#define SCAN_BLK 1024
#define MAX_SB 128   // max scan blocks (ceil(MAXN/1024) = 98)

__device__ __align__(16) float g_xg[MAXN * 32];      // layer-1: x @ g1
__device__ __align__(16) float g_xg2[MAXN * 32];     // layer-2: h @ g2
__device__ __align__(16) float g_rootb[MAXN * 32];   // x @ root1 + b1
__device__ __align__(16) float g_rootb2[MAXN * 32];  // h @ root2 + b2
__device__ __align__(16) float4 g_edges[MAXE];       // (src, gau1, gau2, -) sorted by dst
__device__ int g_cnt[MAXN];                           // in-degree histogram
__device__ int g_rowptr[MAXN + 1];                    // CSR row pointers (by dst)
__device__ int g_cursor[MAXN];                        // scatter cursors
__device__ unsigned long long g_desc[MAX_SB];         // lookback descriptors

// ---------------- CSR build ----------------

// Histogram; block 0 also zeroes the scan descriptors (scan runs strictly after).
__global__ void __launch_bounds__(256) hist_k(const int* __restrict__ ei,
                                              int* __restrict__ cnt,
                                              unsigned long long* __restrict__ desc,
                                              int E) {
    if (blockIdx.x == 0 && threadIdx.x < MAX_SB) desc[threadIdx.x] = 0ULL;
    int e = blockIdx.x * blockDim.x + threadIdx.x;
    if (e < E) atomicAdd(cnt + __ldg(ei + E + e), 1);
}

// Single-pass exclusive scan with decoupled lookback. 98 blocks, all resident.
// desc[b] = (state<<32)|value; state 1=aggregate, 2=inclusive prefix.
__global__ void __launch_bounds__(SCAN_BLK) scan_lb_k(const int* __restrict__ cnt,
                                                      int* __restrict__ rowptr,
                                                      int* __restrict__ cursor,
                                                      unsigned long long* __restrict__ desc,
                                                      int N, int E) {
    __shared__ int sh[SCAN_BLK];
    __shared__ int s_off;
    int t = threadIdx.x, b = blockIdx.x;
    int i = b * SCAN_BLK + t;
    int v = (i < N) ? __ldg(cnt + i) : 0;
    sh[t] = v;
    __syncthreads();
    for (int off = 1; off < SCAN_BLK; off <<= 1) {
        int add = (t >= off) ? sh[t - off] : 0;
        __syncthreads();
        sh[t] += add;
        __syncthreads();
    }
    int incl = sh[t];
    int total = sh[SCAN_BLK - 1];

    if (t == 0) {
        if (b == 0) {
            atomicExch(&desc[0], (2ULL << 32) | (unsigned)total);
            s_off = 0;
        } else {
            atomicExch(&desc[b], (1ULL << 32) | (unsigned)total);
            int off = 0;
            int j = b - 1;
            while (j >= 0) {
                unsigned long long p = atomicAdd(&desc[j], 0ULL);
                unsigned st = (unsigned)(p >> 32);
                if (st == 2u) { off += (int)(unsigned)p; break; }
                if (st == 1u) { off += (int)(unsigned)p; j--; }
                // st == 0: spin (predecessor not yet published)
            }
            atomicExch(&desc[b], (2ULL << 32) | (unsigned)(off + total));
            s_off = off;
        }
    }
    __syncthreads();
    int off = s_off;
    if (i < N) {
        int ex = off + incl - v;
        rowptr[i] = ex;
        cursor[i] = ex;
    }
    if (b == 0 && t == 0) rowptr[N] = E;
}

// Gaussian weights (both layers) + scatter packed records to dst-sorted slots.
__global__ void __launch_bounds__(256) gau_scatter_k(
    const int* __restrict__ ei,
    const float4* __restrict__ ea,    // [E,8] viewed as [E,2] float4
    const float* __restrict__ mu1, const float* __restrict__ s1,
    const float* __restrict__ mu2, const float* __restrict__ s2,
    int* __restrict__ cursor,
    float4* __restrict__ edges, int E) {
    int e = blockIdx.x * blockDim.x + threadIdx.x;
    if (e >= E) return;
    float4 a = ea[e * 2];
    float4 b = ea[e * 2 + 1];
    float v[8] = {a.x, a.y, a.z, a.w, b.x, b.y, b.z, b.w};
    float t1 = 0.f, t2 = 0.f;
#pragma unroll
    for (int d = 0; d < 8; d++) {
        float d1 = v[d] - __ldg(mu1 + d);
        float d2 = v[d] - __ldg(mu2 + d);
        t1 += (-0.5f * d1 * d1) / (1e-15f + __ldg(s1 + d) * __ldg(s1 + d));
        t2 += (-0.5f * d2 * d2) / (1e-15f + __ldg(s2 + d) * __ldg(s2 + d));
    }
    int src = __ldg(ei + e);
    int dst = __ldg(ei + E + e);
    int pos = atomicAdd(cursor + dst, 1);
    float4 rec;
    rec.x = __int_as_float(src);
    rec.y = __expf(t1);
    rec.z = __expf(t2);
    rec.w = 0.f;
    edges[pos] = rec;
}

// ---------------- GEMM layer 1 (register weights) ----------------

__global__ void __launch_bounds__(256) gemm_k(
    const float* __restrict__ xin,
    const float* __restrict__ g,
    const float* __restrict__ root,
    const float* __restrict__ bias,
    float* __restrict__ xg,
    float* __restrict__ rb_out,
    int N) {
    __shared__ float sx[128][32];
    const int t = threadIdx.x;
    const int lane = t & 31;
    const int w = t >> 5;

    float wg[32], wr[32];
#pragma unroll
    for (int k = 0; k < 32; k++) {
        wg[k] = __ldg(g + k * 32 + lane);
        wr[k] = __ldg(root + k * 32 + lane);
    }
    const float bv = __ldg(bias + lane);

    const int base = blockIdx.x * 128;
    const int nrows = min(128, N - base);

    for (int i = t; i < nrows * 32; i += 256)
        sx[i >> 5][i & 31] = xin[(size_t)base * 32 + i];
    __syncthreads();

    for (int r = w; r < nrows; r += 8) {
        float a = 0.0f, b = bv;
#pragma unroll
        for (int k = 0; k < 32; k++) {
            float xv = sx[r][k];
            a = fmaf(xv, wg[k], a);
            b = fmaf(xv, wr[k], b);
        }
        size_t o = (size_t)(base + r) * 32 + lane;
        xg[o] = a;
        rb_out[o] = b;
    }
}

// ---------------- Pull layer 1 fused with GEMM layer 2 ----------------
// One warp per node. Gather-aggregate h (in registers), then compute
// xg2 = h @ g2 and rootb2 = h @ root2 + b2 in-warp via shfl broadcast +
// smem-staged weights. Eliminates the h round-trip and the gemm2 launch.
__global__ void __launch_bounds__(256) pull_gemm_k(
    const int* __restrict__ rowptr,
    const float4* __restrict__ edges,
    const float* __restrict__ xg,      // [N,32] layer-1 transformed feats
    const float* __restrict__ rootb,   // [N,32] layer-1 root term
    const float* __restrict__ g2,
    const float* __restrict__ root2,
    const float* __restrict__ bias2,
    float* __restrict__ xg2,           // [N,32] out
    float* __restrict__ rb2,           // [N,32] out
    int N) {
    __shared__ float swg[1024];
    __shared__ float swr[1024];
    __shared__ float sb[32];
    const int t = threadIdx.x;
    for (int i = t; i < 1024; i += 256) { swg[i] = __ldg(g2 + i); swr[i] = __ldg(root2 + i); }
    if (t < 32) sb[t] = __ldg(bias2 + t);
    __syncthreads();

    int warp = (blockIdx.x * blockDim.x + t) >> 5;
    int lane = t & 31;
    if (warp >= N) return;

    int s = __ldg(rowptr + warp);
    int e = __ldg(rowptr + warp + 1);
    int deg = e - s;

    float acc0 = 0.f, acc1 = 0.f;
    int j = s;
    for (; j + 4 <= e; j += 4) {
        float4 p0 = edges[j], p1 = edges[j + 1], p2 = edges[j + 2], p3 = edges[j + 3];
        float x0 = xg[(size_t)__float_as_int(p0.x) * 32 + lane];
        float x1 = xg[(size_t)__float_as_int(p1.x) * 32 + lane];
        float x2 = xg[(size_t)__float_as_int(p2.x) * 32 + lane];
        float x3 = xg[(size_t)__float_as_int(p3.x) * 32 + lane];
        acc0 = fmaf(p0.y, x0, acc0);
        acc1 = fmaf(p1.y, x1, acc1);
        acc0 = fmaf(p2.y, x2, acc0);
        acc1 = fmaf(p3.y, x3, acc1);
    }
    for (; j < e; j++) {
        float4 p = edges[j];
        float xv = xg[(size_t)__float_as_int(p.x) * 32 + lane];
        acc0 = fmaf(p.y, xv, acc0);
    }

    float rinv = (deg > 0) ? (1.0f / (float)deg) : 0.0f;
    size_t o = (size_t)warp * 32 + lane;
    float h = (acc0 + acc1) * rinv + rootb[o];

    // in-warp GEMM: lane owns output column `lane`
    float a0 = 0.f, a1 = 0.f, b0 = sb[lane], b1 = 0.f;
#pragma unroll
    for (int k = 0; k < 32; k += 2) {
        float hv0 = __shfl_sync(0xffffffffu, h, k);
        float hv1 = __shfl_sync(0xffffffffu, h, k + 1);
        a0 = fmaf(hv0, swg[k * 32 + lane], a0);
        b0 = fmaf(hv0, swr[k * 32 + lane], b0);
        a1 = fmaf(hv1, swg[(k + 1) * 32 + lane], a1);
        b1 = fmaf(hv1, swr[(k + 1) * 32 + lane], b1);
    }
    xg2[o] = a0 + a1;
    rb2[o] = b0 + b1;
}

// ---------------- Pull layer 2 (final) ----------------
template <int LAYER>
__global__ void __launch_bounds__(256) pull_k(
    const int* __restrict__ rowptr,
    const float4* __restrict__ edges,
    const float* __restrict__ xg,
    const float* __restrict__ rootb,
    float* __restrict__ out,
    int N) {
    int warp = (blockIdx.x * blockDim.x + threadIdx.x) >> 5;
    int lane = threadIdx.x & 31;
    if (warp >= N) return;

    int s = __ldg(rowptr + warp);
    int e = __ldg(rowptr + warp + 1);
    int deg = e - s;

    float acc0 = 0.f, acc1 = 0.f;
    int j = s;
    for (; j + 4 <= e; j += 4) {
        float4 p0 = edges[j], p1 = edges[j + 1], p2 = edges[j + 2], p3 = edges[j + 3];
        float x0 = xg[(size_t)__float_as_int(p0.x) * 32 + lane];
        float x1 = xg[(size_t)__float_as_int(p1.x) * 32 + lane];
        float x2 = xg[(size_t)__float_as_int(p2.x) * 32 + lane];
        float x3 = xg[(size_t)__float_as_int(p3.x) * 32 + lane];
        acc0 = fmaf((LAYER == 1) ? p0.y : p0.z, x0, acc0);
        acc1 = fmaf((LAYER == 1) ? p1.y : p1.z, x1, acc1);
        acc0 = fmaf((LAYER == 1) ? p2.y : p2.z, x2, acc0);
        acc1 = fmaf((LAYER == 1) ? p3.y : p3.z, x3, acc1);
    }
    for (; j < e; j++) {
        float4 p = edges[j];
        float xv = xg[(size_t)__float_as_int(p.x) * 32 + lane];
        acc0 = fmaf((LAYER == 1) ? p.y : p.z, xv, acc0);
    }

    float rinv = (deg > 0) ? (1.0f / (float)deg) : 0.0f;
    size_t o = (size_t)warp * 32 + lane;
    out[o] = (acc0 + acc1) * rinv + rootb[o];
}

extern "C" void kernel_launch(void* const* d_in, const int* in_sizes, int n_in,
                              void* d_out, int out_size) {
    const int*   ei  = (const int*)d_in[0];
    const float* ew  = (const float*)d_in[1];
    const float* x   = (const float*)d_in[2];
    const float* g1  = (const float*)d_in[3];
    const float* mu1 = (const float*)d_in[4];
    const float* s1  = (const float*)d_in[5];
    const float* r1  = (const float*)d_in[6];
    const float* b1  = (const float*)d_in[7];
    const float* g2  = (const float*)d_in[8];
    const float* mu2 = (const float*)d_in[9];
    const float* s2  = (const float*)d_in[10];
    const float* r2  = (const float*)d_in[11];
    const float* b2  = (const float*)d_in[12];

    const int E = in_sizes[0] / 2;
    const int N = in_sizes[2] / 32;

    float *xg, *xg2, *rootb, *rootb2;
    float4* edges;
    int *cnt, *rowptr, *cursor;
    unsigned long long* desc;
    cudaGetSymbolAddress((void**)&xg, g_xg);
    cudaGetSymbolAddress((void**)&xg2, g_xg2);
    cudaGetSymbolAddress((void**)&rootb, g_rootb);
    cudaGetSymbolAddress((void**)&rootb2, g_rootb2);
    cudaGetSymbolAddress((void**)&edges, g_edges);
    cudaGetSymbolAddress((void**)&cnt, g_cnt);
    cudaGetSymbolAddress((void**)&rowptr, g_rowptr);
    cudaGetSymbolAddress((void**)&cursor, g_cursor);
    cudaGetSymbolAddress((void**)&desc, g_desc);

    const int nb = (N + SCAN_BLK - 1) / SCAN_BLK;
    const int eb = (E + 255) / 256;
    const int gemm_blocks = (N + 127) / 128;
    const int pull_blocks = (N + 7) / 8;

    // ---- CSR build (shared by both layers) ----
    cudaMemsetAsync(cnt, 0, (size_t)N * sizeof(int), 0);
    hist_k<<<eb, 256>>>(ei, cnt, desc, E);
    scan_lb_k<<<nb, SCAN_BLK>>>(cnt, rowptr, cursor, desc, N, E);
    gau_scatter_k<<<eb, 256>>>(ei, (const float4*)ew, mu1, s1, mu2, s2, cursor, edges, E);

    // ---- layer 1 GEMM, then pull-1 fused with layer-2 GEMM ----
    gemm_k<<<gemm_blocks, 256>>>(x, g1, r1, b1, xg, rootb, N);
    pull_gemm_k<<<pull_blocks, 256>>>(rowptr, edges, xg, rootb, g2, r2, b2, xg2, rootb2, N);

    // ---- layer 2 pull (writes d_out) ----
    pull_k<2><<<pull_blocks, 256>>>(rowptr, edges, xg2, rootb2, (float*)d_out, N);
}

// round 8
// speedup vs baseline: 1.6658x; 1.6658x over previous
#include <cuda_runtime.h>
#include <cstdint>

// N=100000, E=1600000, D=8, K=1, C=32 (dims from in_sizes at runtime).
#define MAXN 100352
#define MAXE 1638400
#define SCAN_BLK 1024
#define MAX_SB 128   // max scan blocks (ceil(MAXN/1024) = 98)

__device__ __align__(16) float g_xg[MAXN * 32];      // x @ g
__device__ __align__(16) float g_rootb[MAXN * 32];   // root term (layer 1)
__device__ __align__(16) float g_rootb2[MAXN * 32];  // root term (layer 2)
__device__ __align__(16) float g_h[MAXN * 32];       // layer-1 output
__device__ __align__(16) float4 g_edges[MAXE];       // packed (src, gau1, gau2, -) sorted by dst
__device__ int g_cnt[MAXN];                           // in-degree histogram
__device__ int g_rowptr[MAXN + 1];                    // CSR row pointers (by dst)
__device__ int g_cursor[MAXN];                        // scatter cursors
__device__ int g_bsum[MAX_SB];                        // scan block sums

// ---------------- CSR build ----------------

__global__ void __launch_bounds__(256) hist_k(const int* __restrict__ ei, int* __restrict__ cnt, int E) {
    int e = blockIdx.x * blockDim.x + threadIdx.x;
    if (e < E) atomicAdd(cnt + __ldg(ei + E + e), 1);
}

// Per-block exclusive scan of 1024 counts; block totals to bsum.
__global__ void __launch_bounds__(SCAN_BLK) scan1_k(const int* __restrict__ cnt,
                                                    int* __restrict__ rowptr,
                                                    int* __restrict__ bsum, int N) {
    __shared__ int sh[SCAN_BLK];
    int t = threadIdx.x;
    int i = blockIdx.x * SCAN_BLK + t;
    int v = (i < N) ? cnt[i] : 0;
    sh[t] = v;
    __syncthreads();
    for (int off = 1; off < SCAN_BLK; off <<= 1) {
        int add = (t >= off) ? sh[t - off] : 0;
        __syncthreads();
        sh[t] += add;
        __syncthreads();
    }
    if (i < N) rowptr[i] = sh[t] - v;  // exclusive
    if (t == SCAN_BLK - 1) bsum[blockIdx.x] = sh[t];
}

// Exclusive scan of block sums (single block).
__global__ void __launch_bounds__(MAX_SB) scan2_k(int* __restrict__ bsum, int nb) {
    __shared__ int sh[MAX_SB];
    int t = threadIdx.x;
    int v = (t < nb) ? bsum[t] : 0;
    sh[t] = v;
    __syncthreads();
    for (int off = 1; off < MAX_SB; off <<= 1) {
        int add = (t >= off) ? sh[t - off] : 0;
        __syncthreads();
        sh[t] += add;
        __syncthreads();
    }
    if (t < nb) bsum[t] = sh[t] - v;
}

// Add block offsets; init cursors; set rowptr[N]=E.
__global__ void __launch_bounds__(SCAN_BLK) scan3_k(int* __restrict__ rowptr,
                                                    int* __restrict__ cursor,
                                                    const int* __restrict__ bsum,
                                                    int N, int E) {
    int i = blockIdx.x * SCAN_BLK + threadIdx.x;
    if (i < N) {
        int v = rowptr[i] + bsum[blockIdx.x];
        rowptr[i] = v;
        cursor[i] = v;
    }
    if (i == 0) rowptr[N] = E;
}

// Compute both layers' gaussian weights and scatter packed edge records
// (src, gau1, gau2) to their dst-sorted slot. One 16B write per edge.
__global__ void __launch_bounds__(256) gau_scatter_k(
    const int* __restrict__ ei,
    const float4* __restrict__ ea,    // [E,8] viewed as [E,2] float4
    const float* __restrict__ mu1, const float* __restrict__ s1,
    const float* __restrict__ mu2, const float* __restrict__ s2,
    int* __restrict__ cursor,
    float4* __restrict__ edges, int E) {
    int e = blockIdx.x * blockDim.x + threadIdx.x;
    if (e >= E) return;
    float4 a = ea[e * 2];
    float4 b = ea[e * 2 + 1];
    float v[8] = {a.x, a.y, a.z, a.w, b.x, b.y, b.z, b.w};
    float t1 = 0.f, t2 = 0.f;
#pragma unroll
    for (int d = 0; d < 8; d++) {
        float d1 = v[d] - __ldg(mu1 + d);
        float d2 = v[d] - __ldg(mu2 + d);
        t1 += (-0.5f * d1 * d1) / (1e-15f + __ldg(s1 + d) * __ldg(s1 + d));
        t2 += (-0.5f * d2 * d2) / (1e-15f + __ldg(s2 + d) * __ldg(s2 + d));
    }
    int src = __ldg(ei + e);
    int dst = __ldg(ei + E + e);
    int pos = atomicAdd(cursor + dst, 1);
    float4 rec;
    rec.x = __int_as_float(src);
    rec.y = __expf(t1);
    rec.z = __expf(t2);
    rec.w = 0.f;
    edges[pos] = rec;
}

// ---------------- GEMM (register weights) ----------------

__global__ void __launch_bounds__(256) gemm_k(
    const float* __restrict__ xin,
    const float* __restrict__ g,
    const float* __restrict__ root,
    const float* __restrict__ bias,
    float* __restrict__ xg,
    float* __restrict__ rb_out,
    int N) {
    __shared__ float sx[128][32];
    const int t = threadIdx.x;
    const int lane = t & 31;
    const int w = t >> 5;

    float wg[32], wr[32];
#pragma unroll
    for (int k = 0; k < 32; k++) {
        wg[k] = __ldg(g + k * 32 + lane);
        wr[k] = __ldg(root + k * 32 + lane);
    }
    const float bv = __ldg(bias + lane);

    const int base = blockIdx.x * 128;
    const int nrows = min(128, N - base);

    for (int i = t; i < nrows * 32; i += 256)
        sx[i >> 5][i & 31] = xin[(size_t)base * 32 + i];
    __syncthreads();

    for (int r = w; r < nrows; r += 8) {
        float a = 0.0f, b = bv;
#pragma unroll
        for (int k = 0; k < 32; k++) {
            float xv = sx[r][k];
            a = fmaf(xv, wg[k], a);
            b = fmaf(xv, wr[k], b);
        }
        size_t o = (size_t)(base + r) * 32 + lane;
        xg[o] = a;
        rb_out[o] = b;
    }
}

// ---------------- Pull aggregation (atomic-free, cooperative records) ----------------
// One warp per dst node; lane = channel. Edge records are loaded COALESCED
// (lane j takes record j of the chunk: 4 wavefronts / 32 edges instead of 1
// wavefront per edge) and redistributed via shfl. Gather loop keeps the
// round-4 unroll-4 / dual-accumulator shape for MLP.
template <int LAYER>
__global__ void __launch_bounds__(256) pull_k(
    const int* __restrict__ rowptr,
    const float4* __restrict__ edges,
    const float* __restrict__ xg,     // [N,32]
    const float* __restrict__ rootb,  // [N,32]
    float* __restrict__ out,          // [N,32]
    int N) {
    int warp = (blockIdx.x * blockDim.x + threadIdx.x) >> 5;
    int lane = threadIdx.x & 31;
    if (warp >= N) return;

    int s = __ldg(rowptr + warp);
    int e = __ldg(rowptr + warp + 1);
    int deg = e - s;

    float acc0 = 0.f, acc1 = 0.f;

    for (int j = s; j < e; j += 32) {
        int m = min(32, e - j);
        // cooperative coalesced record load: lane i -> record j+i
        int   si = 0;
        float gv = 0.f;
        if (lane < m) {
            float4 r = edges[j + lane];
            si = __float_as_int(r.x);
            gv = (LAYER == 1) ? r.y : r.z;
        }
        int k = 0;
        for (; k + 4 <= m; k += 4) {
            int   s0 = __shfl_sync(0xffffffffu, si, k);
            int   s1 = __shfl_sync(0xffffffffu, si, k + 1);
            int   s2 = __shfl_sync(0xffffffffu, si, k + 2);
            int   s3 = __shfl_sync(0xffffffffu, si, k + 3);
            float g0 = __shfl_sync(0xffffffffu, gv, k);
            float g1 = __shfl_sync(0xffffffffu, gv, k + 1);
            float g2 = __shfl_sync(0xffffffffu, gv, k + 2);
            float g3 = __shfl_sync(0xffffffffu, gv, k + 3);
            float x0 = xg[(size_t)s0 * 32 + lane];
            float x1 = xg[(size_t)s1 * 32 + lane];
            float x2 = xg[(size_t)s2 * 32 + lane];
            float x3 = xg[(size_t)s3 * 32 + lane];
            acc0 = fmaf(g0, x0, acc0);
            acc1 = fmaf(g1, x1, acc1);
            acc0 = fmaf(g2, x2, acc0);
            acc1 = fmaf(g3, x3, acc1);
        }
        for (; k < m; k++) {
            int   sk = __shfl_sync(0xffffffffu, si, k);
            float gk = __shfl_sync(0xffffffffu, gv, k);
            acc0 = fmaf(gk, xg[(size_t)sk * 32 + lane], acc0);
        }
    }

    float rinv = (deg > 0) ? (1.0f / (float)deg) : 0.0f;
    size_t o = (size_t)warp * 32 + lane;
    out[o] = (acc0 + acc1) * rinv + rootb[o];
}

extern "C" void kernel_launch(void* const* d_in, const int* in_sizes, int n_in,
                              void* d_out, int out_size) {
    const int*   ei  = (const int*)d_in[0];
    const float* ew  = (const float*)d_in[1];
    const float* x   = (const float*)d_in[2];
    const float* g1  = (const float*)d_in[3];
    const float* mu1 = (const float*)d_in[4];
    const float* s1  = (const float*)d_in[5];
    const float* r1  = (const float*)d_in[6];
    const float* b1  = (const float*)d_in[7];
    const float* g2  = (const float*)d_in[8];
    const float* mu2 = (const float*)d_in[9];
    const float* s2  = (const float*)d_in[10];
    const float* r2  = (const float*)d_in[11];
    const float* b2  = (const float*)d_in[12];

    const int E = in_sizes[0] / 2;
    const int N = in_sizes[2] / 32;

    float *xg, *rootb, *rootb2, *h;
    float4* edges;
    int *cnt, *rowptr, *cursor, *bsum;
    cudaGetSymbolAddress((void**)&xg, g_xg);
    cudaGetSymbolAddress((void**)&rootb, g_rootb);
    cudaGetSymbolAddress((void**)&rootb2, g_rootb2);
    cudaGetSymbolAddress((void**)&h, g_h);
    cudaGetSymbolAddress((void**)&edges, g_edges);
    cudaGetSymbolAddress((void**)&cnt, g_cnt);
    cudaGetSymbolAddress((void**)&rowptr, g_rowptr);
    cudaGetSymbolAddress((void**)&cursor, g_cursor);
    cudaGetSymbolAddress((void**)&bsum, g_bsum);

    const int nb = (N + SCAN_BLK - 1) / SCAN_BLK;
    const int eb = (E + 255) / 256;
    const int gemm_blocks = (N + 127) / 128;
    const int pull_blocks = (N + 7) / 8;

    // ---- CSR build (shared by both layers) ----
    cudaMemsetAsync(cnt, 0, (size_t)N * sizeof(int), 0);
    hist_k<<<eb, 256>>>(ei, cnt, E);
    scan1_k<<<nb, SCAN_BLK>>>(cnt, rowptr, bsum, N);
    scan2_k<<<1, MAX_SB>>>(bsum, nb);
    scan3_k<<<nb, SCAN_BLK>>>(rowptr, cursor, bsum, N, E);
    gau_scatter_k<<<eb, 256>>>(ei, (const float4*)ew, mu1, s1, mu2, s2, cursor, edges, E);

    // ---- layer 1 ----
    gemm_k<<<gemm_blocks, 256>>>(x, g1, r1, b1, xg, rootb, N);
    pull_k<1><<<pull_blocks, 256>>>(rowptr, edges, xg, rootb, h, N);

    // ---- layer 2 ----
    gemm_k<<<gemm_blocks, 256>>>(h, g2, r2, b2, xg, rootb2, N);
    pull_k<2><<<pull_blocks, 256>>>(rowptr, edges, xg, rootb2, (float*)d_out, N);
}

// round 9
// speedup vs baseline: 1.7487x; 1.0498x over previous
#include <cuda_runtime.h>
#include <cuda_fp16.h>
#include <cstdint>

// N=100000, E=1600000, D=8, K=1, C=32 (dims from in_sizes at runtime).
#define MAXN 100352
#define MAXE 1638400
#define SCAN_BLK 1024
#define MAX_SB 128   // max scan blocks (ceil(MAXN/1024) = 98)

__device__ __align__(16) __half g_xgh[MAXN * 32];    // x @ g (fp16 gather payload)
__device__ __align__(16) float g_rootb[MAXN * 32];   // root term (layer 1)
__device__ __align__(16) float g_rootb2[MAXN * 32];  // root term (layer 2)
__device__ __align__(16) float g_h[MAXN * 32];       // layer-1 output (fp32)
__device__ __align__(16) float4 g_edges[MAXE];       // packed (src, gau1, gau2, -) sorted by dst
__device__ int g_cnt[MAXN];                           // in-degree histogram
__device__ int g_rowptr[MAXN + 1];                    // CSR row pointers (by dst)
__device__ int g_cursor[MAXN];                        // scatter cursors
__device__ int g_bsum[MAX_SB];                        // scan block sums

// ---------------- CSR build ----------------

__global__ void __launch_bounds__(256) hist_k(const int* __restrict__ ei, int* __restrict__ cnt, int E) {
    int e = blockIdx.x * blockDim.x + threadIdx.x;
    if (e < E) atomicAdd(cnt + __ldg(ei + E + e), 1);
}

// Per-block exclusive scan of 1024 counts; block totals to bsum.
__global__ void __launch_bounds__(SCAN_BLK) scan1_k(const int* __restrict__ cnt,
                                                    int* __restrict__ rowptr,
                                                    int* __restrict__ bsum, int N) {
    __shared__ int sh[SCAN_BLK];
    int t = threadIdx.x;
    int i = blockIdx.x * SCAN_BLK + t;
    int v = (i < N) ? cnt[i] : 0;
    sh[t] = v;
    __syncthreads();
    for (int off = 1; off < SCAN_BLK; off <<= 1) {
        int add = (t >= off) ? sh[t - off] : 0;
        __syncthreads();
        sh[t] += add;
        __syncthreads();
    }
    if (i < N) rowptr[i] = sh[t] - v;  // exclusive
    if (t == SCAN_BLK - 1) bsum[blockIdx.x] = sh[t];
}

// Exclusive scan of block sums (single block).
__global__ void __launch_bounds__(MAX_SB) scan2_k(int* __restrict__ bsum, int nb) {
    __shared__ int sh[MAX_SB];
    int t = threadIdx.x;
    int v = (t < nb) ? bsum[t] : 0;
    sh[t] = v;
    __syncthreads();
    for (int off = 1; off < MAX_SB; off <<= 1) {
        int add = (t >= off) ? sh[t - off] : 0;
        __syncthreads();
        sh[t] += add;
        __syncthreads();
    }
    if (t < nb) bsum[t] = sh[t] - v;
}

// Add block offsets; init cursors; set rowptr[N]=E.
__global__ void __launch_bounds__(SCAN_BLK) scan3_k(int* __restrict__ rowptr,
                                                    int* __restrict__ cursor,
                                                    const int* __restrict__ bsum,
                                                    int N, int E) {
    int i = blockIdx.x * SCAN_BLK + threadIdx.x;
    if (i < N) {
        int v = rowptr[i] + bsum[blockIdx.x];
        rowptr[i] = v;
        cursor[i] = v;
    }
    if (i == 0) rowptr[N] = E;
}

// Compute both layers' gaussian weights and scatter packed edge records
// (src, gau1, gau2) to their dst-sorted slot. One 16B write per edge.
__global__ void __launch_bounds__(256) gau_scatter_k(
    const int* __restrict__ ei,
    const float4* __restrict__ ea,    // [E,8] viewed as [E,2] float4
    const float* __restrict__ mu1, const float* __restrict__ s1,
    const float* __restrict__ mu2, const float* __restrict__ s2,
    int* __restrict__ cursor,
    float4* __restrict__ edges, int E) {
    int e = blockIdx.x * blockDim.x + threadIdx.x;
    if (e >= E) return;
    float4 a = ea[e * 2];
    float4 b = ea[e * 2 + 1];
    float v[8] = {a.x, a.y, a.z, a.w, b.x, b.y, b.z, b.w};
    float t1 = 0.f, t2 = 0.f;
#pragma unroll
    for (int d = 0; d < 8; d++) {
        float d1 = v[d] - __ldg(mu1 + d);
        float d2 = v[d] - __ldg(mu2 + d);
        t1 += (-0.5f * d1 * d1) / (1e-15f + __ldg(s1 + d) * __ldg(s1 + d));
        t2 += (-0.5f * d2 * d2) / (1e-15f + __ldg(s2 + d) * __ldg(s2 + d));
    }
    int src = __ldg(ei + e);
    int dst = __ldg(ei + E + e);
    int pos = atomicAdd(cursor + dst, 1);
    float4 rec;
    rec.x = __int_as_float(src);
    rec.y = __expf(t1);
    rec.z = __expf(t2);
    rec.w = 0.f;
    edges[pos] = rec;
}

// ---------------- GEMM (register weights, fp16 xg output) ----------------

__global__ void __launch_bounds__(256) gemm_k(
    const float* __restrict__ xin,
    const float* __restrict__ g,
    const float* __restrict__ root,
    const float* __restrict__ bias,
    __half* __restrict__ xg,
    float* __restrict__ rb_out,
    int N) {
    __shared__ float sx[128][32];
    const int t = threadIdx.x;
    const int lane = t & 31;
    const int w = t >> 5;

    float wg[32], wr[32];
#pragma unroll
    for (int k = 0; k < 32; k++) {
        wg[k] = __ldg(g + k * 32 + lane);
        wr[k] = __ldg(root + k * 32 + lane);
    }
    const float bv = __ldg(bias + lane);

    const int base = blockIdx.x * 128;
    const int nrows = min(128, N - base);

    for (int i = t; i < nrows * 32; i += 256)
        sx[i >> 5][i & 31] = xin[(size_t)base * 32 + i];
    __syncthreads();

    for (int r = w; r < nrows; r += 8) {
        float a = 0.0f, b = bv;
#pragma unroll
        for (int k = 0; k < 32; k++) {
            float xv = sx[r][k];
            a = fmaf(xv, wg[k], a);
            b = fmaf(xv, wr[k], b);
        }
        size_t o = (size_t)(base + r) * 32 + lane;
        xg[o] = __float2half_rn(a);
        rb_out[o] = b;
    }
}

// ---------------- Pull aggregation (cooperative records, fp16 gather) ----------------
// One warp per dst node; lane = channel. Records loaded coalesced (lane i ->
// record j+i) and redistributed via shfl; xg rows gathered as fp16 (64B/edge),
// accumulated in fp32.
template <int LAYER>
__global__ void __launch_bounds__(256) pull_k(
    const int* __restrict__ rowptr,
    const float4* __restrict__ edges,
    const __half* __restrict__ xg,    // [N,32] fp16
    const float* __restrict__ rootb,  // [N,32]
    float* __restrict__ out,          // [N,32]
    int N) {
    int warp = (blockIdx.x * blockDim.x + threadIdx.x) >> 5;
    int lane = threadIdx.x & 31;
    if (warp >= N) return;

    int s = __ldg(rowptr + warp);
    int e = __ldg(rowptr + warp + 1);
    int deg = e - s;

    float acc0 = 0.f, acc1 = 0.f;

    for (int j = s; j < e; j += 32) {
        int m = min(32, e - j);
        // cooperative coalesced record load: lane i -> record j+i
        int   si = 0;
        float gv = 0.f;
        if (lane < m) {
            float4 r = edges[j + lane];
            si = __float_as_int(r.x);
            gv = (LAYER == 1) ? r.y : r.z;
        }
        int k = 0;
        for (; k + 4 <= m; k += 4) {
            int   s0 = __shfl_sync(0xffffffffu, si, k);
            int   s1 = __shfl_sync(0xffffffffu, si, k + 1);
            int   s2 = __shfl_sync(0xffffffffu, si, k + 2);
            int   s3 = __shfl_sync(0xffffffffu, si, k + 3);
            float g0 = __shfl_sync(0xffffffffu, gv, k);
            float g1 = __shfl_sync(0xffffffffu, gv, k + 1);
            float g2 = __shfl_sync(0xffffffffu, gv, k + 2);
            float g3 = __shfl_sync(0xffffffffu, gv, k + 3);
            float x0 = __half2float(__ldg(xg + (size_t)s0 * 32 + lane));
            float x1 = __half2float(__ldg(xg + (size_t)s1 * 32 + lane));
            float x2 = __half2float(__ldg(xg + (size_t)s2 * 32 + lane));
            float x3 = __half2float(__ldg(xg + (size_t)s3 * 32 + lane));
            acc0 = fmaf(g0, x0, acc0);
            acc1 = fmaf(g1, x1, acc1);
            acc0 = fmaf(g2, x2, acc0);
            acc1 = fmaf(g3, x3, acc1);
        }
        for (; k < m; k++) {
            int   sk = __shfl_sync(0xffffffffu, si, k);
            float gk = __shfl_sync(0xffffffffu, gv, k);
            acc0 = fmaf(gk, __half2float(__ldg(xg + (size_t)sk * 32 + lane)), acc0);
        }
    }

    float rinv = (deg > 0) ? (1.0f / (float)deg) : 0.0f;
    size_t o = (size_t)warp * 32 + lane;
    out[o] = (acc0 + acc1) * rinv + rootb[o];
}

extern "C" void kernel_launch(void* const* d_in, const int* in_sizes, int n_in,
                              void* d_out, int out_size) {
    const int*   ei  = (const int*)d_in[0];
    const float* ew  = (const float*)d_in[1];
    const float* x   = (const float*)d_in[2];
    const float* g1  = (const float*)d_in[3];
    const float* mu1 = (const float*)d_in[4];
    const float* s1  = (const float*)d_in[5];
    const float* r1  = (const float*)d_in[6];
    const float* b1  = (const float*)d_in[7];
    const float* g2  = (const float*)d_in[8];
    const float* mu2 = (const float*)d_in[9];
    const float* s2  = (const float*)d_in[10];
    const float* r2  = (const float*)d_in[11];
    const float* b2  = (const float*)d_in[12];

    const int E = in_sizes[0] / 2;
    const int N = in_sizes[2] / 32;

    __half* xgh;
    float *rootb, *rootb2, *h;
    float4* edges;
    int *cnt, *rowptr, *cursor, *bsum;
    cudaGetSymbolAddress((void**)&xgh, g_xgh);
    cudaGetSymbolAddress((void**)&rootb, g_rootb);
    cudaGetSymbolAddress((void**)&rootb2, g_rootb2);
    cudaGetSymbolAddress((void**)&h, g_h);
    cudaGetSymbolAddress((void**)&edges, g_edges);
    cudaGetSymbolAddress((void**)&cnt, g_cnt);
    cudaGetSymbolAddress((void**)&rowptr, g_rowptr);
    cudaGetSymbolAddress((void**)&cursor, g_cursor);
    cudaGetSymbolAddress((void**)&bsum, g_bsum);

    const int nb = (N + SCAN_BLK - 1) / SCAN_BLK;
    const int eb = (E + 255) / 256;
    const int gemm_blocks = (N + 127) / 128;
    const int pull_blocks = (N + 7) / 8;

    // ---- CSR build (shared by both layers) ----
    cudaMemsetAsync(cnt, 0, (size_t)N * sizeof(int), 0);
    hist_k<<<eb, 256>>>(ei, cnt, E);
    scan1_k<<<nb, SCAN_BLK>>>(cnt, rowptr, bsum, N);
    scan2_k<<<1, MAX_SB>>>(bsum, nb);
    scan3_k<<<nb, SCAN_BLK>>>(rowptr, cursor, bsum, N, E);
    gau_scatter_k<<<eb, 256>>>(ei, (const float4*)ew, mu1, s1, mu2, s2, cursor, edges, E);

    // ---- layer 1 ----
    gemm_k<<<gemm_blocks, 256>>>(x, g1, r1, b1, xgh, rootb, N);
    pull_k<1><<<pull_blocks, 256>>>(rowptr, edges, xgh, rootb, h, N);

    // ---- layer 2 ----
    gemm_k<<<gemm_blocks, 256>>>(h, g2, r2, b2, xgh, rootb2, N);
    pull_k<2><<<pull_blocks, 256>>>(rowptr, edges, xgh, rootb2, (float*)d_out, N);
}

// round 10
// speedup vs baseline: 1.7991x; 1.0288x over previous
#include <cuda_runtime.h>
#include <cuda_fp16.h>
#include <cstdint>

// N=100000, E=1600000, D=8, K=1, C=32 (dims from in_sizes at runtime).
#define MAXN 100352
#define MAXE 1638400
#define SCAN_BLK 1024
#define MAX_SB 128   // max scan blocks (ceil(MAXN/1024) = 98)

__device__ __align__(16) __half g_xgh[MAXN * 32];    // x @ g (fp16 gather payload)
__device__ __align__(16) float g_rootb[MAXN * 32];   // root term (layer 1)
__device__ __align__(16) float g_rootb2[MAXN * 32];  // root term (layer 2)
__device__ __align__(16) float g_h[MAXN * 32];       // layer-1 output (fp32)
__device__ __align__(16) uint2 g_edges[MAXE];        // (src, half2(gau1,gau2)) sorted by dst
__device__ int g_cnt[MAXN];                           // in-degree histogram
__device__ int g_rowptr[MAXN + 1];                    // CSR row pointers (by dst)
__device__ int g_cursor[MAXN];                        // scatter cursors
__device__ int g_bsum[MAX_SB];                        // scan block sums

// ---------------- CSR build ----------------

__global__ void __launch_bounds__(256) hist_k(const int* __restrict__ ei, int* __restrict__ cnt, int E) {
    int e = blockIdx.x * blockDim.x + threadIdx.x;
    if (e < E) atomicAdd(cnt + __ldg(ei + E + e), 1);
}

// Per-block exclusive scan of 1024 counts; block totals to bsum.
__global__ void __launch_bounds__(SCAN_BLK) scan1_k(const int* __restrict__ cnt,
                                                    int* __restrict__ rowptr,
                                                    int* __restrict__ bsum, int N) {
    __shared__ int sh[SCAN_BLK];
    int t = threadIdx.x;
    int i = blockIdx.x * SCAN_BLK + t;
    int v = (i < N) ? cnt[i] : 0;
    sh[t] = v;
    __syncthreads();
    for (int off = 1; off < SCAN_BLK; off <<= 1) {
        int add = (t >= off) ? sh[t - off] : 0;
        __syncthreads();
        sh[t] += add;
        __syncthreads();
    }
    if (i < N) rowptr[i] = sh[t] - v;  // exclusive
    if (t == SCAN_BLK - 1) bsum[blockIdx.x] = sh[t];
}

// Exclusive scan of block sums (single block).
__global__ void __launch_bounds__(MAX_SB) scan2_k(int* __restrict__ bsum, int nb) {
    __shared__ int sh[MAX_SB];
    int t = threadIdx.x;
    int v = (t < nb) ? bsum[t] : 0;
    sh[t] = v;
    __syncthreads();
    for (int off = 1; off < MAX_SB; off <<= 1) {
        int add = (t >= off) ? sh[t - off] : 0;
        __syncthreads();
        sh[t] += add;
        __syncthreads();
    }
    if (t < nb) bsum[t] = sh[t] - v;
}

// Add block offsets; init cursors; set rowptr[N]=E.
__global__ void __launch_bounds__(SCAN_BLK) scan3_k(int* __restrict__ rowptr,
                                                    int* __restrict__ cursor,
                                                    const int* __restrict__ bsum,
                                                    int N, int E) {
    int i = blockIdx.x * SCAN_BLK + threadIdx.x;
    if (i < N) {
        int v = rowptr[i] + bsum[blockIdx.x];
        rowptr[i] = v;
        cursor[i] = v;
    }
    if (i == 0) rowptr[N] = E;
}

// Gaussian weights (both layers, packed half2) + scatter 8B records to the
// dst-sorted slot.
__global__ void __launch_bounds__(256) gau_scatter_k(
    const int* __restrict__ ei,
    const float4* __restrict__ ea,    // [E,8] viewed as [E,2] float4
    const float* __restrict__ mu1, const float* __restrict__ s1,
    const float* __restrict__ mu2, const float* __restrict__ s2,
    int* __restrict__ cursor,
    uint2* __restrict__ edges, int E) {
    int e = blockIdx.x * blockDim.x + threadIdx.x;
    if (e >= E) return;
    float4 a = ea[e * 2];
    float4 b = ea[e * 2 + 1];
    float v[8] = {a.x, a.y, a.z, a.w, b.x, b.y, b.z, b.w};
    float t1 = 0.f, t2 = 0.f;
#pragma unroll
    for (int d = 0; d < 8; d++) {
        float d1 = v[d] - __ldg(mu1 + d);
        float d2 = v[d] - __ldg(mu2 + d);
        t1 += (-0.5f * d1 * d1) / (1e-15f + __ldg(s1 + d) * __ldg(s1 + d));
        t2 += (-0.5f * d2 * d2) / (1e-15f + __ldg(s2 + d) * __ldg(s2 + d));
    }
    int src = __ldg(ei + e);
    int dst = __ldg(ei + E + e);
    int pos = atomicAdd(cursor + dst, 1);
    __half2 gp = __floats2half2_rn(__expf(t1), __expf(t2));
    uint2 rec;
    rec.x = (unsigned)src;
    rec.y = *reinterpret_cast<unsigned*>(&gp);
    edges[pos] = rec;
}

// ---------------- GEMM (register weights, fp16 xg output) ----------------

__global__ void __launch_bounds__(256) gemm_k(
    const float* __restrict__ xin,
    const float* __restrict__ g,
    const float* __restrict__ root,
    const float* __restrict__ bias,
    __half* __restrict__ xg,
    float* __restrict__ rb_out,
    int N) {
    __shared__ float sx[128][32];
    const int t = threadIdx.x;
    const int lane = t & 31;
    const int w = t >> 5;

    float wg[32], wr[32];
#pragma unroll
    for (int k = 0; k < 32; k++) {
        wg[k] = __ldg(g + k * 32 + lane);
        wr[k] = __ldg(root + k * 32 + lane);
    }
    const float bv = __ldg(bias + lane);

    const int base = blockIdx.x * 128;
    const int nrows = min(128, N - base);

    for (int i = t; i < nrows * 32; i += 256)
        sx[i >> 5][i & 31] = xin[(size_t)base * 32 + i];
    __syncthreads();

    for (int r = w; r < nrows; r += 8) {
        float a = 0.0f, b = bv;
#pragma unroll
        for (int k = 0; k < 32; k++) {
            float xv = sx[r][k];
            a = fmaf(xv, wg[k], a);
            b = fmaf(xv, wr[k], b);
        }
        size_t o = (size_t)(base + r) * 32 + lane;
        xg[o] = __float2half_rn(a);
        rb_out[o] = b;
    }
}

// ---------------- Pull aggregation (cooperative 8B records, fp16 gather) ----------------
// One warp per dst node; lane = channel. Records loaded coalesced (lane i ->
// record j+i, 8B each) and redistributed via shfl; xg rows gathered as fp16
// (64B/edge), accumulated in fp32.
template <int LAYER>
__global__ void __launch_bounds__(256) pull_k(
    const int* __restrict__ rowptr,
    const uint2* __restrict__ edges,
    const __half* __restrict__ xg,    // [N,32] fp16
    const float* __restrict__ rootb,  // [N,32]
    float* __restrict__ out,          // [N,32]
    int N) {
    int warp = (blockIdx.x * blockDim.x + threadIdx.x) >> 5;
    int lane = threadIdx.x & 31;
    if (warp >= N) return;

    int s = __ldg(rowptr + warp);
    int e = __ldg(rowptr + warp + 1);
    int deg = e - s;

    float acc0 = 0.f, acc1 = 0.f;

    for (int j = s; j < e; j += 32) {
        int m = min(32, e - j);
        // cooperative coalesced record load: lane i -> record j+i
        int   si = 0;
        float gv = 0.f;
        if (lane < m) {
            uint2 r = edges[j + lane];
            si = (int)r.x;
            __half2 gp = *reinterpret_cast<__half2*>(&r.y);
            gv = (LAYER == 1) ? __low2float(gp) : __high2float(gp);
        }
        int k = 0;
        for (; k + 4 <= m; k += 4) {
            int   s0 = __shfl_sync(0xffffffffu, si, k);
            int   s1 = __shfl_sync(0xffffffffu, si, k + 1);
            int   s2 = __shfl_sync(0xffffffffu, si, k + 2);
            int   s3 = __shfl_sync(0xffffffffu, si, k + 3);
            float g0 = __shfl_sync(0xffffffffu, gv, k);
            float g1 = __shfl_sync(0xffffffffu, gv, k + 1);
            float g2 = __shfl_sync(0xffffffffu, gv, k + 2);
            float g3 = __shfl_sync(0xffffffffu, gv, k + 3);
            float x0 = __half2float(__ldg(xg + (size_t)s0 * 32 + lane));
            float x1 = __half2float(__ldg(xg + (size_t)s1 * 32 + lane));
            float x2 = __half2float(__ldg(xg + (size_t)s2 * 32 + lane));
            float x3 = __half2float(__ldg(xg + (size_t)s3 * 32 + lane));
            acc0 = fmaf(g0, x0, acc0);
            acc1 = fmaf(g1, x1, acc1);
            acc0 = fmaf(g2, x2, acc0);
            acc1 = fmaf(g3, x3, acc1);
        }
        for (; k < m; k++) {
            int   sk = __shfl_sync(0xffffffffu, si, k);
            float gk = __shfl_sync(0xffffffffu, gv, k);
            acc0 = fmaf(gk, __half2float(__ldg(xg + (size_t)sk * 32 + lane)), acc0);
        }
    }

    float rinv = (deg > 0) ? (1.0f / (float)deg) : 0.0f;
    size_t o = (size_t)warp * 32 + lane;
    out[o] = (acc0 + acc1) * rinv + rootb[o];
}

extern "C" void kernel_launch(void* const* d_in, const int* in_sizes, int n_in,
                              void* d_out, int out_size) {
    const int*   ei  = (const int*)d_in[0];
    const float* ew  = (const float*)d_in[1];
    const float* x   = (const float*)d_in[2];
    const float* g1  = (const float*)d_in[3];
    const float* mu1 = (const float*)d_in[4];
    const float* s1  = (const float*)d_in[5];
    const float* r1  = (const float*)d_in[6];
    const float* b1  = (const float*)d_in[7];
    const float* g2  = (const float*)d_in[8];
    const float* mu2 = (const float*)d_in[9];
    const float* s2  = (const float*)d_in[10];
    const float* r2  = (const float*)d_in[11];
    const float* b2  = (const float*)d_in[12];

    const int E = in_sizes[0] / 2;
    const int N = in_sizes[2] / 32;

    __half* xgh;
    float *rootb, *rootb2, *h;
    uint2* edges;
    int *cnt, *rowptr, *cursor, *bsum;
    cudaGetSymbolAddress((void**)&xgh, g_xgh);
    cudaGetSymbolAddress((void**)&rootb, g_rootb);
    cudaGetSymbolAddress((void**)&rootb2, g_rootb2);
    cudaGetSymbolAddress((void**)&h, g_h);
    cudaGetSymbolAddress((void**)&edges, g_edges);
    cudaGetSymbolAddress((void**)&cnt, g_cnt);
    cudaGetSymbolAddress((void**)&rowptr, g_rowptr);
    cudaGetSymbolAddress((void**)&cursor, g_cursor);
    cudaGetSymbolAddress((void**)&bsum, g_bsum);

    const int nb = (N + SCAN_BLK - 1) / SCAN_BLK;
    const int eb = (E + 255) / 256;
    const int gemm_blocks = (N + 127) / 128;
    const int pull_blocks = (N + 7) / 8;

    // ---- CSR build (shared by both layers) ----
    cudaMemsetAsync(cnt, 0, (size_t)N * sizeof(int), 0);
    hist_k<<<eb, 256>>>(ei, cnt, E);
    scan1_k<<<nb, SCAN_BLK>>>(cnt, rowptr, bsum, N);
    scan2_k<<<1, MAX_SB>>>(bsum, nb);
    scan3_k<<<nb, SCAN_BLK>>>(rowptr, cursor, bsum, N, E);
    gau_scatter_k<<<eb, 256>>>(ei, (const float4*)ew, mu1, s1, mu2, s2, cursor, edges, E);

    // ---- layer 1 ----
    gemm_k<<<gemm_blocks, 256>>>(x, g1, r1, b1, xgh, rootb, N);
    pull_k<1><<<pull_blocks, 256>>>(rowptr, edges, xgh, rootb, h, N);

    // ---- layer 2 ----
    gemm_k<<<gemm_blocks, 256>>>(h, g2, r2, b2, xgh, rootb2, N);
    pull_k<2><<<pull_blocks, 256>>>(rowptr, edges, xgh, rootb2, (float*)d_out, N);
}

// round 11
// speedup vs baseline: 1.8759x; 1.0427x over previous
#include <cuda_runtime.h>
#include <cuda_fp16.h>
#include <cstdint>

// N=100000, E=1600000, D=8, K=1, C=32 (dims from in_sizes at runtime).
#define MAXN 100352
#define MAXE 1638400
#define SCAN_BLK 1024
#define MAX_SB 128   // max scan blocks (ceil(MAXN/1024) = 98)

__device__ __align__(16) __half g_xgh[MAXN * 32];    // x @ g (fp16 gather payload)
__device__ __align__(16) float g_rootb[MAXN * 32];   // root term (layer 1)
__device__ __align__(16) float g_rootb2[MAXN * 32];  // root term (layer 2)
__device__ __align__(16) float g_h[MAXN * 32];       // layer-1 output (fp32)
__device__ __align__(16) uint2 g_edges[MAXE];        // (src, half2(gau1,gau2)) sorted by dst
__device__ int g_cnt[MAXN];                           // in-degree histogram
__device__ int g_rowptr[MAXN + 1];                    // CSR row pointers (by dst)
__device__ int g_cursor[MAXN];                        // scatter cursors
__device__ int g_bsum[MAX_SB];                        // scan block sums

// ---------------- CSR build ----------------

__global__ void __launch_bounds__(256) hist_k(const int* __restrict__ ei, int* __restrict__ cnt, int E) {
    int e = blockIdx.x * blockDim.x + threadIdx.x;
    if (e < E) atomicAdd(cnt + __ldg(ei + E + e), 1);
}

// Per-block exclusive scan of 1024 counts; block totals to bsum.
__global__ void __launch_bounds__(SCAN_BLK) scan1_k(const int* __restrict__ cnt,
                                                    int* __restrict__ rowptr,
                                                    int* __restrict__ bsum, int N) {
    __shared__ int sh[SCAN_BLK];
    int t = threadIdx.x;
    int i = blockIdx.x * SCAN_BLK + t;
    int v = (i < N) ? cnt[i] : 0;
    sh[t] = v;
    __syncthreads();
    for (int off = 1; off < SCAN_BLK; off <<= 1) {
        int add = (t >= off) ? sh[t - off] : 0;
        __syncthreads();
        sh[t] += add;
        __syncthreads();
    }
    if (i < N) rowptr[i] = sh[t] - v;  // exclusive
    if (t == SCAN_BLK - 1) bsum[blockIdx.x] = sh[t];
}

// Fused scan2+scan3: each block computes its own block-offset (warp-reduced
// prefix over <=98 block sums), then applies it and initializes cursors.
__global__ void __launch_bounds__(SCAN_BLK) scan23_k(int* __restrict__ rowptr,
                                                     int* __restrict__ cursor,
                                                     const int* __restrict__ bsum,
                                                     int N, int E) {
    __shared__ int s_off;
    int t = threadIdx.x;
    if (t < 32) {
        int acc = 0;
        for (int j = t; j < blockIdx.x; j += 32) acc += __ldg(bsum + j);
        acc += __shfl_xor_sync(0xffffffffu, acc, 16);
        acc += __shfl_xor_sync(0xffffffffu, acc, 8);
        acc += __shfl_xor_sync(0xffffffffu, acc, 4);
        acc += __shfl_xor_sync(0xffffffffu, acc, 2);
        acc += __shfl_xor_sync(0xffffffffu, acc, 1);
        if (t == 0) s_off = acc;
    }
    __syncthreads();
    int i = blockIdx.x * SCAN_BLK + t;
    if (i < N) {
        int v = rowptr[i] + s_off;
        rowptr[i] = v;
        cursor[i] = v;
    }
    if (i == 0) rowptr[N] = E;
}

// Gaussian weights (both layers, packed half2) + scatter 8B records to the
// dst-sorted slot.
__global__ void __launch_bounds__(256) gau_scatter_k(
    const int* __restrict__ ei,
    const float4* __restrict__ ea,    // [E,8] viewed as [E,2] float4
    const float* __restrict__ mu1, const float* __restrict__ s1,
    const float* __restrict__ mu2, const float* __restrict__ s2,
    int* __restrict__ cursor,
    uint2* __restrict__ edges, int E) {
    int e = blockIdx.x * blockDim.x + threadIdx.x;
    if (e >= E) return;
    float4 a = ea[e * 2];
    float4 b = ea[e * 2 + 1];
    float v[8] = {a.x, a.y, a.z, a.w, b.x, b.y, b.z, b.w};
    float t1 = 0.f, t2 = 0.f;
#pragma unroll
    for (int d = 0; d < 8; d++) {
        float d1 = v[d] - __ldg(mu1 + d);
        float d2 = v[d] - __ldg(mu2 + d);
        t1 += (-0.5f * d1 * d1) / (1e-15f + __ldg(s1 + d) * __ldg(s1 + d));
        t2 += (-0.5f * d2 * d2) / (1e-15f + __ldg(s2 + d) * __ldg(s2 + d));
    }
    int src = __ldg(ei + e);
    int dst = __ldg(ei + E + e);
    int pos = atomicAdd(cursor + dst, 1);
    __half2 gp = __floats2half2_rn(__expf(t1), __expf(t2));
    uint2 rec;
    rec.x = (unsigned)src;
    rec.y = *reinterpret_cast<unsigned*>(&gp);
    edges[pos] = rec;
}

// ---------------- GEMM (register weights, fp16 xg output) ----------------

__global__ void __launch_bounds__(256) gemm_k(
    const float* __restrict__ xin,
    const float* __restrict__ g,
    const float* __restrict__ root,
    const float* __restrict__ bias,
    __half* __restrict__ xg,
    float* __restrict__ rb_out,
    int N) {
    __shared__ float sx[128][32];
    const int t = threadIdx.x;
    const int lane = t & 31;
    const int w = t >> 5;

    float wg[32], wr[32];
#pragma unroll
    for (int k = 0; k < 32; k++) {
        wg[k] = __ldg(g + k * 32 + lane);
        wr[k] = __ldg(root + k * 32 + lane);
    }
    const float bv = __ldg(bias + lane);

    const int base = blockIdx.x * 128;
    const int nrows = min(128, N - base);

    for (int i = t; i < nrows * 32; i += 256)
        sx[i >> 5][i & 31] = xin[(size_t)base * 32 + i];
    __syncthreads();

    for (int r = w; r < nrows; r += 8) {
        float a = 0.0f, b = bv;
#pragma unroll
        for (int k = 0; k < 32; k++) {
            float xv = sx[r][k];
            a = fmaf(xv, wg[k], a);
            b = fmaf(xv, wr[k], b);
        }
        size_t o = (size_t)(base + r) * 32 + lane;
        xg[o] = __float2half_rn(a);
        rb_out[o] = b;
    }
}

// ---------------- Pull aggregation: 2 edges per warp-instruction ----------------
// One warp per dst node. Lanes 0-15 process edge A, lanes 16-31 edge B; each
// lane owns 2 channels as one __half2 (4B load). Gather wavefronts halve vs
// 1-edge-per-instruction. Records loaded coalesced, redistributed via shfl.
// Epilogue folds the two half-warps with shfl_xor(16); lanes 0-15 write float2.
template <int LAYER>
__global__ void __launch_bounds__(256) pull_k(
    const int* __restrict__ rowptr,
    const uint2* __restrict__ edges,
    const __half2* __restrict__ xg,   // [N,16] half2 rows
    const float2* __restrict__ rootb, // [N,16] float2 rows
    float2* __restrict__ out,         // [N,16] float2 rows
    int N) {
    int warp = (blockIdx.x * blockDim.x + threadIdx.x) >> 5;
    int lane = threadIdx.x & 31;
    if (warp >= N) return;

    const int c2 = lane & 15;     // channel-pair index (channels 2*c2, 2*c2+1)
    const int which = lane >> 4;  // 0 -> even edge, 1 -> odd edge

    int s = __ldg(rowptr + warp);
    int e = __ldg(rowptr + warp + 1);
    int deg = e - s;

    float ax0 = 0.f, ay0 = 0.f, ax1 = 0.f, ay1 = 0.f;

    for (int j = s; j < e; j += 32) {
        int m = min(32, e - j);
        // cooperative coalesced record load: lane i -> record j+i
        int   si = 0;
        float gv = 0.f;
        if (lane < m) {
            uint2 r = edges[j + lane];
            si = (int)r.x;
            __half2 gp = *reinterpret_cast<__half2*>(&r.y);
            gv = (LAYER == 1) ? __low2float(gp) : __high2float(gp);
        }
        int k = 0;
        for (; k + 4 <= m; k += 4) {
            int   sa = __shfl_sync(0xffffffffu, si, k + which);
            float ga = __shfl_sync(0xffffffffu, gv, k + which);
            int   sb = __shfl_sync(0xffffffffu, si, k + 2 + which);
            float gb = __shfl_sync(0xffffffffu, gv, k + 2 + which);
            float2 xa = __half22float2(__ldg(xg + (size_t)sa * 16 + c2));
            float2 xb = __half22float2(__ldg(xg + (size_t)sb * 16 + c2));
            ax0 = fmaf(ga, xa.x, ax0);
            ay0 = fmaf(ga, xa.y, ay0);
            ax1 = fmaf(gb, xb.x, ax1);
            ay1 = fmaf(gb, xb.y, ay1);
        }
        for (; k + 2 <= m; k += 2) {
            int   sa = __shfl_sync(0xffffffffu, si, k + which);
            float ga = __shfl_sync(0xffffffffu, gv, k + which);
            float2 xa = __half22float2(__ldg(xg + (size_t)sa * 16 + c2));
            ax0 = fmaf(ga, xa.x, ax0);
            ay0 = fmaf(ga, xa.y, ay0);
        }
        if (k < m) {  // single leftover edge: only the 'which==0' half contributes
            int   sa = __shfl_sync(0xffffffffu, si, k);
            float ga = __shfl_sync(0xffffffffu, gv, k);
            if (which == 0) {
                float2 xa = __half22float2(__ldg(xg + (size_t)sa * 16 + c2));
                ax0 = fmaf(ga, xa.x, ax0);
                ay0 = fmaf(ga, xa.y, ay0);
            }
        }
    }

    float ax = ax0 + ax1;
    float ay = ay0 + ay1;
    ax += __shfl_xor_sync(0xffffffffu, ax, 16);
    ay += __shfl_xor_sync(0xffffffffu, ay, 16);

    if (lane < 16) {
        float rinv = (deg > 0) ? (1.0f / (float)deg) : 0.0f;
        size_t o = (size_t)warp * 16 + c2;
        float2 r = __ldg(rootb + o);
        float2 ov;
        ov.x = ax * rinv + r.x;
        ov.y = ay * rinv + r.y;
        out[o] = ov;
    }
}

extern "C" void kernel_launch(void* const* d_in, const int* in_sizes, int n_in,
                              void* d_out, int out_size) {
    const int*   ei  = (const int*)d_in[0];
    const float* ew  = (const float*)d_in[1];
    const float* x   = (const float*)d_in[2];
    const float* g1  = (const float*)d_in[3];
    const float* mu1 = (const float*)d_in[4];
    const float* s1  = (const float*)d_in[5];
    const float* r1  = (const float*)d_in[6];
    const float* b1  = (const float*)d_in[7];
    const float* g2  = (const float*)d_in[8];
    const float* mu2 = (const float*)d_in[9];
    const float* s2  = (const float*)d_in[10];
    const float* r2  = (const float*)d_in[11];
    const float* b2  = (const float*)d_in[12];

    const int E = in_sizes[0] / 2;
    const int N = in_sizes[2] / 32;

    __half* xgh;
    float *rootb, *rootb2, *h;
    uint2* edges;
    int *cnt, *rowptr, *cursor, *bsum;
    cudaGetSymbolAddress((void**)&xgh, g_xgh);
    cudaGetSymbolAddress((void**)&rootb, g_rootb);
    cudaGetSymbolAddress((void**)&rootb2, g_rootb2);
    cudaGetSymbolAddress((void**)&h, g_h);
    cudaGetSymbolAddress((void**)&edges, g_edges);
    cudaGetSymbolAddress((void**)&cnt, g_cnt);
    cudaGetSymbolAddress((void**)&rowptr, g_rowptr);
    cudaGetSymbolAddress((void**)&cursor, g_cursor);
    cudaGetSymbolAddress((void**)&bsum, g_bsum);

    const int nb = (N + SCAN_BLK - 1) / SCAN_BLK;
    const int eb = (E + 255) / 256;
    const int gemm_blocks = (N + 127) / 128;
    const int pull_blocks = (N + 7) / 8;

    // ---- CSR build (shared by both layers) ----
    cudaMemsetAsync(cnt, 0, (size_t)N * sizeof(int), 0);
    hist_k<<<eb, 256>>>(ei, cnt, E);
    scan1_k<<<nb, SCAN_BLK>>>(cnt, rowptr, bsum, N);
    scan23_k<<<nb, SCAN_BLK>>>(rowptr, cursor, bsum, N, E);
    gau_scatter_k<<<eb, 256>>>(ei, (const float4*)ew, mu1, s1, mu2, s2, cursor, edges, E);

    // ---- layer 1 ----
    gemm_k<<<gemm_blocks, 256>>>(x, g1, r1, b1, xgh, rootb, N);
    pull_k<1><<<pull_blocks, 256>>>(rowptr, edges, (const __half2*)xgh,
                                    (const float2*)rootb, (float2*)h, N);

    // ---- layer 2 ----
    gemm_k<<<gemm_blocks, 256>>>(h, g2, r2, b2, xgh, rootb2, N);
    pull_k<2><<<pull_blocks, 256>>>(rowptr, edges, (const __half2*)xgh,
                                    (const float2*)rootb2, (float2*)d_out, N);
}